// round 1
// baseline (speedup 1.0000x reference)
#include <cuda_runtime.h>
#include <math.h>

#define BI 8
#define PP 2000
#define NC 81
#define CPP 80
#define CAP 16384
#define KPRE 2048
#define DET 100
#define W_IMGF 1333.0f
#define H_IMGF 800.0f
#define SCORE_T 0.05f
#define NMS_T 0.5f
#define XFORM_CLIP 4.135166556742356f

// ---------------- device scratch (no allocations allowed) ----------------
__device__ int g_cnt[BI];
__device__ unsigned long long g_keys[BI][CAP];
__device__ float4 g_top_b[BI][KPRE];
__device__ float g_top_s[BI][KPRE];
__device__ int g_top_l[BI][KPRE];
__device__ int g_top_v[BI][KPRE];
__device__ int g_keep[BI][KPRE];

// ---------------- helpers ----------------
__device__ __forceinline__ float4 decode_clip(float4 pr, const float* __restrict__ rel) {
    float w = pr.z - pr.x;
    float h = pr.w - pr.y;
    float cx = pr.x + 0.5f * w;
    float cy = pr.y + 0.5f * h;
    float dx = rel[0] / 10.0f;
    float dy = rel[1] / 10.0f;
    float dw = fminf(rel[2] / 5.0f, XFORM_CLIP);
    float dh = fminf(rel[3] / 5.0f, XFORM_CLIP);
    float pcx = dx * w + cx;
    float pcy = dy * h + cy;
    float pw = expf(dw) * w;
    float ph = expf(dh) * h;
    float x1 = pcx - 0.5f * pw;
    float y1 = pcy - 0.5f * ph;
    float x2 = pcx + 0.5f * pw;
    float y2 = pcy + 0.5f * ph;
    x1 = fminf(fmaxf(x1, 0.0f), W_IMGF);
    y1 = fminf(fmaxf(y1, 0.0f), H_IMGF);
    x2 = fminf(fmaxf(x2, 0.0f), W_IMGF);
    y2 = fminf(fmaxf(y2, 0.0f), H_IMGF);
    return make_float4(x1, y1, x2, y2);
}

// ---------------- K0: init ----------------
__global__ void k_init() {
    int t = blockIdx.x * blockDim.x + threadIdx.x;
    if (t < BI) g_cnt[t] = 0;
    int total = BI * CAP;
    for (int i = t; i < total; i += gridDim.x * blockDim.x) {
        ((unsigned long long*)g_keys)[i] = 0ull;
    }
}

// ---------------- K1: softmax + candidate generation ----------------
__global__ void k_gen(const float* __restrict__ logits,
                      const float* __restrict__ boxreg,
                      const float* __restrict__ props) {
    int gw = (blockIdx.x * blockDim.x + threadIdx.x) >> 5;
    int lane = threadIdx.x & 31;
    if (gw >= BI * PP) return;
    int b = gw / PP;
    int p = gw - b * PP;

    const float* lrow = logits + (long long)gw * NC;
    float l0 = lrow[lane];
    float l1 = lrow[lane + 32];
    float l2 = (lane + 64 < NC) ? lrow[lane + 64] : -1e30f;

    float m = fmaxf(l0, fmaxf(l1, l2));
    #pragma unroll
    for (int o = 16; o; o >>= 1) m = fmaxf(m, __shfl_xor_sync(0xffffffffu, m, o));

    float e0 = expf(l0 - m);
    float e1 = expf(l1 - m);
    float e2 = (lane + 64 < NC) ? expf(l2 - m) : 0.0f;
    float s = e0 + e1 + e2;
    #pragma unroll
    for (int o = 16; o; o >>= 1) s += __shfl_xor_sync(0xffffffffu, s, o);

    float4 pr = reinterpret_cast<const float4*>(props)[gw];

    #pragma unroll
    for (int r = 0; r < 3; r++) {
        int ci = lane + r * 32;
        float e = (r == 0) ? e0 : ((r == 1) ? e1 : e2);
        if (ci >= 1 && ci < NC) {
            float score = e / s;
            if (score > SCORE_T) {
                const float* rel = boxreg + ((long long)gw * NC + ci) * 4;
                float4 bx = decode_clip(pr, rel);
                if ((bx.z - bx.x) >= 0.01f && (bx.w - bx.y) >= 0.01f) {
                    int pos = atomicAdd(&g_cnt[b], 1);
                    if (pos < CAP) {
                        unsigned idx = (unsigned)(p * CPP + (ci - 1));
                        g_keys[b][pos] =
                            ((unsigned long long)__float_as_uint(score) << 32) |
                            (unsigned long long)(0xFFFFFFFFu - idx);
                    }
                }
            }
        }
    }
}

// ---------------- K2: per-image bitonic sort of 16384 keys (ascending) ----------------
__global__ void k_sort() {
    extern __shared__ unsigned long long sk[];
    int b = blockIdx.x;
    for (int i = threadIdx.x; i < CAP; i += blockDim.x) sk[i] = g_keys[b][i];
    __syncthreads();
    for (int k = 2; k <= CAP; k <<= 1) {
        for (int j = k >> 1; j; j >>= 1) {
            for (int i = threadIdx.x; i < CAP; i += blockDim.x) {
                int ixj = i ^ j;
                if (ixj > i) {
                    unsigned long long a = sk[i], c = sk[ixj];
                    bool up = ((i & k) == 0);
                    if ((a > c) == up) { sk[i] = c; sk[ixj] = a; }
                }
            }
            __syncthreads();
        }
    }
    for (int i = threadIdx.x; i < CAP; i += blockDim.x) g_keys[b][i] = sk[i];
}

// ---------------- K3: build top-2048 arrays (re-decode boxes) ----------------
__global__ void k_build(const float* __restrict__ boxreg,
                        const float* __restrict__ props) {
    int b = blockIdx.x;
    for (int t = threadIdx.x; t < KPRE; t += blockDim.x) {
        unsigned long long key = g_keys[b][CAP - 1 - t];
        if (key != 0ull) {
            unsigned idx = 0xFFFFFFFFu - (unsigned)(key & 0xFFFFFFFFull);
            float score = __uint_as_float((unsigned)(key >> 32));
            int p = idx / CPP;
            int ci = idx % CPP + 1;
            int gw = b * PP + p;
            float4 pr = reinterpret_cast<const float4*>(props)[gw];
            const float* rel = boxreg + ((long long)gw * NC + ci) * 4;
            float4 bx = decode_clip(pr, rel);
            g_top_b[b][t] = bx;
            g_top_s[b][t] = score;
            g_top_l[b][t] = ci;
            g_top_v[b][t] = 1;
        } else {
            g_top_b[b][t] = make_float4(0.f, 0.f, 0.f, 0.f);
            g_top_s[b][t] = -1.0f;
            g_top_l[b][t] = 0;
            g_top_v[b][t] = 0;
        }
        g_keep[b][t] = 0;
    }
}

// ---------------- K4: per-class greedy NMS (one warp per class) ----------------
// batched_nms offset (label*1334 > image extent) means cross-class IoU == 0,
// so global greedy NMS over the sorted list == independent per-class greedy NMS
// with the same within-class visiting order.
__global__ void k_nms() {
    __shared__ unsigned short lists[8][KPRE];  // 8 warps/block
    int b = blockIdx.x;
    int wid = threadIdx.x >> 5;
    int lane = threadIdx.x & 31;
    int cls = blockIdx.y * 8 + wid;  // 0..79
    int label = cls + 1;
    unsigned short* list = lists[wid];

    // build ordered per-class candidate list (t ascending == score descending)
    int n = 0;
    for (int base = 0; base < KPRE; base += 32) {
        int t = base + lane;
        bool match = (g_top_l[b][t] == label);
        unsigned bal = __ballot_sync(0xffffffffu, match);
        if (match) list[n + __popc(bal & ((1u << lane) - 1u))] = (unsigned short)t;
        n += __popc(bal);
    }

    // greedy NMS: entry e lives at lane (e&31), bit (e>>5) of the keep mask
    unsigned long long kept = ~0ull;
    for (int i = 0; i < n; i++) {
        int il = i & 31, is = i >> 5;
        unsigned ki = __shfl_sync(0xffffffffu, (unsigned)((kept >> is) & 1ull), il);
        if (!ki) continue;
        int ti = list[i];
        float4 bi = g_top_b[b][ti];
        float ai = fmaxf(bi.z - bi.x, 0.f) * fmaxf(bi.w - bi.y, 0.f);
        for (int sslot = is; sslot * 32 + lane < n; sslot++) {
            int e = sslot * 32 + lane;
            if (e > i && ((kept >> sslot) & 1ull)) {
                int te = list[e];
                float4 be = g_top_b[b][te];
                float ae = fmaxf(be.z - be.x, 0.f) * fmaxf(be.w - be.y, 0.f);
                float lx = fmaxf(bi.x, be.x), ly = fmaxf(bi.y, be.y);
                float rx = fminf(bi.z, be.z), ry = fminf(bi.w, be.w);
                float iw = fmaxf(rx - lx, 0.f), ih = fmaxf(ry - ly, 0.f);
                float inter = iw * ih;
                float uni = ai + ae - inter;
                float iou = inter / fmaxf(uni, 1e-9f);
                if (iou > NMS_T) kept &= ~(1ull << sslot);
            }
        }
    }
    for (int sslot = 0; sslot * 32 + lane < n; sslot++) {
        int e = sslot * 32 + lane;
        g_keep[b][list[e]] = (int)((kept >> sslot) & 1ull);
    }
}

// ---------------- K5: final top-100 + output ----------------
// layout: det_b [8*100*4] | det_s [800] | det_l [800] | det_valid [800]
__global__ void k_final(float* __restrict__ out) {
    __shared__ unsigned long long sk[KPRE];
    int b = blockIdx.x;
    for (int t = threadIdx.x; t < KPRE; t += blockDim.x) {
        float v = g_keep[b][t] ? g_top_s[b][t] : -1.0f;
        unsigned u = __float_as_uint(v);
        u = (u & 0x80000000u) ? ~u : (u | 0x80000000u);  // order-preserving map
        sk[t] = ((unsigned long long)u << 32) |
                (unsigned long long)(0xFFFFFFFFu - (unsigned)t);
    }
    __syncthreads();
    for (int k = 2; k <= KPRE; k <<= 1) {
        for (int j = k >> 1; j; j >>= 1) {
            for (int i = threadIdx.x; i < KPRE; i += blockDim.x) {
                int ixj = i ^ j;
                if (ixj > i) {
                    unsigned long long a = sk[i], c = sk[ixj];
                    bool up = ((i & k) == 0);
                    if ((a > c) == up) { sk[i] = c; sk[ixj] = a; }
                }
            }
            __syncthreads();
        }
    }
    for (int t = threadIdx.x; t < DET; t += blockDim.x) {
        unsigned long long key = sk[KPRE - 1 - t];
        unsigned idx = 0xFFFFFFFFu - (unsigned)(key & 0xFFFFFFFFull);
        float sc = g_keep[b][idx] ? g_top_s[b][idx] : -1.0f;
        float4 bx = g_top_b[b][idx];
        out[(b * DET + t) * 4 + 0] = bx.x;
        out[(b * DET + t) * 4 + 1] = bx.y;
        out[(b * DET + t) * 4 + 2] = bx.z;
        out[(b * DET + t) * 4 + 3] = bx.w;
        out[BI * DET * 4 + b * DET + t] = sc;
        out[BI * DET * 5 + b * DET + t] = (float)g_top_l[b][idx];
        out[BI * DET * 6 + b * DET + t] = (sc > 0.0f) ? 1.0f : 0.0f;
    }
}

// ---------------- launch ----------------
extern "C" void kernel_launch(void* const* d_in, const int* in_sizes, int n_in,
                              void* d_out, int out_size) {
    const float* logits = (const float*)d_in[0];
    const float* boxreg = (const float*)d_in[1];
    const float* props  = (const float*)d_in[2];
    float* out = (float*)d_out;

    cudaFuncSetAttribute(k_sort, cudaFuncAttributeMaxDynamicSharedMemorySize, CAP * 8);

    k_init<<<512, 256>>>();
    k_gen<<<(BI * PP * 32 + 255) / 256, 256>>>(logits, boxreg, props);
    k_sort<<<BI, 1024, CAP * 8>>>();
    k_build<<<BI, 256>>>(boxreg, props);
    k_nms<<<dim3(BI, 10), 256>>>();
    k_final<<<BI, 1024>>>(out);
}

// round 3
// speedup vs baseline: 2.2656x; 2.2656x over previous
#include <cuda_runtime.h>
#include <math.h>

typedef unsigned long long u64;
typedef unsigned int u32;

#define BI 8
#define PP 2000
#define NC 81
#define CPP 80
#define CAP 16384
#define KPRE 2048
#define DET 100
#define NBIN 8192
#define BINSHIFT 50   // key>>50 == float bits [31:18]; sign==0 for scores>0
#define BCAP 8192
#define W_IMGF 1333.0f
#define H_IMGF 800.0f
#define SCORE_T 0.05f
#define NMS_T 0.5f
#define XFORM_CLIP 4.135166556742356f

// ---------------- device scratch ----------------
__device__ int g_cnt[BI];
__device__ u64 g_keys[BI][CAP];

// ---------------- helpers ----------------
__device__ __forceinline__ float4 decode_clip(float4 pr, float4 rel) {
    float w = pr.z - pr.x;
    float h = pr.w - pr.y;
    float cx = pr.x + 0.5f * w;
    float cy = pr.y + 0.5f * h;
    float dx = rel.x / 10.0f;
    float dy = rel.y / 10.0f;
    float dw = fminf(rel.z / 5.0f, XFORM_CLIP);
    float dh = fminf(rel.w / 5.0f, XFORM_CLIP);
    float pcx = dx * w + cx;
    float pcy = dy * h + cy;
    float pw = expf(dw) * w;
    float ph = expf(dh) * h;
    float x1 = fminf(fmaxf(pcx - 0.5f * pw, 0.0f), W_IMGF);
    float y1 = fminf(fmaxf(pcy - 0.5f * ph, 0.0f), H_IMGF);
    float x2 = fminf(fmaxf(pcx + 0.5f * pw, 0.0f), W_IMGF);
    float y2 = fminf(fmaxf(pcy + 0.5f * ph, 0.0f), H_IMGF);
    return make_float4(x1, y1, x2, y2);
}

// ---------------- K0: reset counters only ----------------
__global__ void k_reset() {
    if (threadIdx.x < BI) g_cnt[threadIdx.x] = 0;
}

// ---------------- K1: softmax + candidate gen (warp-aggregated atomics) --
__global__ void k_gen(const float* __restrict__ logits,
                      const float* __restrict__ boxreg,
                      const float* __restrict__ props) {
    int gw = (blockIdx.x * blockDim.x + threadIdx.x) >> 5;
    int lane = threadIdx.x & 31;
    if (gw >= BI * PP) return;
    int b = gw / PP;
    int p = gw - b * PP;

    const float* lrow = logits + (long long)gw * NC;
    float l0 = lrow[lane];
    float l1 = lrow[lane + 32];
    float l2 = (lane + 64 < NC) ? lrow[lane + 64] : -1e30f;

    float m = fmaxf(l0, fmaxf(l1, l2));
    #pragma unroll
    for (int o = 16; o; o >>= 1) m = fmaxf(m, __shfl_xor_sync(0xffffffffu, m, o));
    float e0 = expf(l0 - m);
    float e1 = expf(l1 - m);
    float e2 = (lane + 64 < NC) ? expf(l2 - m) : 0.0f;
    float s = e0 + e1 + e2;
    #pragma unroll
    for (int o = 16; o; o >>= 1) s += __shfl_xor_sync(0xffffffffu, s, o);

    float4 pr = reinterpret_cast<const float4*>(props)[gw];

    bool ok[3];
    float sc[3];
    #pragma unroll
    for (int r = 0; r < 3; r++) {
        int ci = lane + r * 32;
        float e = (r == 0) ? e0 : ((r == 1) ? e1 : e2);
        ok[r] = false;
        sc[r] = 0.0f;
        if (ci >= 1 && ci < NC) {
            float score = e / s;
            if (score > SCORE_T) {
                float4 rel = reinterpret_cast<const float4*>(boxreg)[(long long)gw * NC + ci];
                float4 bx = decode_clip(pr, rel);
                if ((bx.z - bx.x) >= 0.01f && (bx.w - bx.y) >= 0.01f) {
                    ok[r] = true;
                    sc[r] = score;
                }
            }
        }
    }

    unsigned bal[3];
    bal[0] = __ballot_sync(0xffffffffu, ok[0]);
    bal[1] = __ballot_sync(0xffffffffu, ok[1]);
    bal[2] = __ballot_sync(0xffffffffu, ok[2]);
    int cnt0 = __popc(bal[0]);
    int cnt1 = __popc(bal[1]);
    int tot = cnt0 + cnt1 + __popc(bal[2]);
    int base = 0;
    if (lane == 0 && tot) base = atomicAdd(&g_cnt[b], tot);
    base = __shfl_sync(0xffffffffu, base, 0);

    unsigned below = (1u << lane) - 1u;
    #pragma unroll
    for (int r = 0; r < 3; r++) {
        if (ok[r]) {
            int off = __popc(bal[r] & below) + ((r > 0) ? cnt0 : 0) + ((r > 1) ? cnt1 : 0);
            int slot = base + off;
            if (slot < CAP) {
                unsigned idx = (unsigned)(p * CPP + (lane + r * 32 - 1));
                g_keys[b][slot] = ((u64)__float_as_uint(sc[r]) << 32) |
                                  (u64)(0xFFFFFFFFu - idx);
            }
        }
    }
}

// ---------------- K2: mega kernel: select -> sort -> decode -> NMS -> out
// SMEM (dynamic, 144KB):
//   [0,16K)   u64 keys[2048]
//   [16K,..)  union:
//     phase A: int hist[8192] (32KB); u64 bound[8192] (64KB)
//     phase B: float4 boxes[2048] (32KB) | float scores[2048] (8KB) |
//              uchar labels[2048] | ushort clist[2048] | ushort chcnt[64*80] |
//              int classoff[80]+classcnt[80] | uchar keep[2048]
__global__ void __launch_bounds__(1024, 1)
k_mega(const float* __restrict__ boxreg,
       const float* __restrict__ props,
       float* __restrict__ out) {
    extern __shared__ char sm[];
    u64* keys = (u64*)sm;
    char* reg2 = sm + 16384;
    int* hist = (int*)reg2;
    u64* bound = (u64*)reg2;
    float4* boxes = (float4*)reg2;
    float* scores = (float*)(reg2 + 32768);
    unsigned char* labels = (unsigned char*)(reg2 + 40960);
    unsigned short* clist = (unsigned short*)(reg2 + 43008);
    unsigned short* chcnt = (unsigned short*)(reg2 + 47104);
    int* classoff = (int*)(reg2 + 57600);
    int* classcnt = classoff + 80;
    unsigned char* keep = (unsigned char*)(reg2 + 58368);

    __shared__ int s_t, s_A, s_R, aCtr, bCtr, wsum[32];

    const int tid = threadIdx.x;
    const int lane = tid & 31;
    const int wid = tid >> 5;
    const int b = blockIdx.x;
    const int cnt = min(g_cnt[b], CAP);
    const int K = min(cnt, KPRE);

    // ---- A1: histogram on float bits [30:18] (monotone in key) ----
    for (int i = tid; i < NBIN; i += 1024) hist[i] = 0;
    if (tid == 0) { s_t = 0x7FFFFFFF; s_A = 0; s_R = 0; aCtr = 0; bCtr = 0; }
    __syncthreads();
    for (int i = tid; i < cnt; i += 1024) {
        int bin = (int)(g_keys[b][i] >> BINSHIFT);
        atomicAdd(&hist[bin], 1);
    }
    __syncthreads();

    // ---- A2: descending block scan; find rank-K crossing bin ----
    {
        const int BPT = NBIN / 1024;  // 8 bins per thread
        int localsum = 0;
        int bhi = NBIN - 1 - BPT * tid;
        #pragma unroll
        for (int j = 0; j < BPT; j++) localsum += hist[bhi - j];
        int v = localsum;
        #pragma unroll
        for (int o = 1; o < 32; o <<= 1) {
            int n = __shfl_up_sync(0xffffffffu, v, o);
            if (lane >= o) v += n;
        }
        if (lane == 31) wsum[wid] = v;
        __syncthreads();
        if (wid == 0) {
            int w = wsum[lane];
            #pragma unroll
            for (int o = 1; o < 32; o <<= 1) {
                int n = __shfl_up_sync(0xffffffffu, w, o);
                if (lane >= o) w += n;
            }
            wsum[lane] = w;
        }
        __syncthreads();
        int incl = v + ((wid > 0) ? wsum[wid - 1] : 0);
        int excl = incl - localsum;
        if (K > 0 && excl < K && K <= incl) {
            int run = excl;
            for (int j = 0; j < BPT; j++) {
                int bin = bhi - j;
                int h = hist[bin];
                if (run < K && K <= run + h) { s_t = bin; s_A = run; s_R = K - run; }
                run += h;
            }
        }
    }
    __syncthreads();
    const int tbin = s_t, A = s_A, R = s_R;
    __syncthreads();  // hist dead after this; bound overlays it

    // ---- A3: compact above-threshold keys; gather boundary bin ----
    for (int i = tid; i < cnt; i += 1024) {
        u64 key = g_keys[b][i];
        int bin = (int)(key >> BINSHIFT);
        if (bin > tbin) {
            int pos = atomicAdd(&aCtr, 1);
            keys[pos] = key;
        } else if (bin == tbin) {
            int pos = atomicAdd(&bCtr, 1);
            if (pos < BCAP) bound[pos] = key;
        }
    }
    __syncthreads();

    // ---- A4: sort boundary bin desc, keep top R ----
    int m = min(bCtr, BCAP);
    if (m > 0) {
        int M = 1;
        while (M < m) M <<= 1;
        for (int i = m + tid; i < M; i += 1024) bound[i] = 0ull;
        __syncthreads();
        for (int k2 = 2; k2 <= M; k2 <<= 1) {
            for (int j = k2 >> 1; j; j >>= 1) {
                for (int i = tid; i < M; i += 1024) {
                    int ixj = i ^ j;
                    if (ixj > i) {
                        u64 a = bound[i], c = bound[ixj];
                        bool up = ((i & k2) == 0);
                        if ((a < c) == up) { bound[i] = c; bound[ixj] = a; }
                    }
                }
                __syncthreads();
            }
        }
        for (int i = tid; i < R; i += 1024) keys[A + i] = bound[i];
    }
    for (int i = K + tid; i < KPRE; i += 1024) keys[i] = 0ull;
    __syncthreads();

    // ---- A5: descending bitonic sort of 2048 selected keys ----
    for (int k2 = 2; k2 <= KPRE; k2 <<= 1) {
        for (int j = k2 >> 1; j; j >>= 1) {
            for (int i = tid; i < KPRE; i += 1024) {
                int ixj = i ^ j;
                if (ixj > i) {
                    u64 a = keys[i], c = keys[ixj];
                    bool up = ((i & k2) == 0);
                    if ((a < c) == up) { keys[i] = c; keys[ixj] = a; }
                }
            }
            __syncthreads();
        }
    }

    // ---- B1: decode boxes/scores/labels ----
    for (int t = tid; t < KPRE; t += 1024) {
        keep[t] = 0;
        if (t < K) {
            u64 key = keys[t];
            unsigned idx = 0xFFFFFFFFu - (unsigned)(key & 0xFFFFFFFFull);
            int p = idx / CPP;
            int cm1 = idx - p * CPP;
            int gw = b * PP + p;
            float4 pr = reinterpret_cast<const float4*>(props)[gw];
            float4 rel = reinterpret_cast<const float4*>(boxreg)[(long long)gw * NC + cm1 + 1];
            boxes[t] = decode_clip(pr, rel);
            scores[t] = __uint_as_float((unsigned)(key >> 32));
            labels[t] = (unsigned char)cm1;
        } else {
            boxes[t] = make_float4(0.f, 0.f, 0.f, 0.f);
            scores[t] = -1.0f;
            labels[t] = 0xFF;
        }
    }
    for (int i = tid; i < 64 * 80; i += 1024) chcnt[i] = 0;
    __syncthreads();

    // ---- B2: stable counting sort by class (match_any ranks) ----
    for (int c = wid; c < 64; c += 32) {
        int t = c * 32 + lane;
        unsigned L = labels[t];
        unsigned mask = __match_any_sync(0xffffffffu, L);
        int leader = __ffs(mask) - 1;
        if (L < 80 && lane == leader) chcnt[c * 80 + L] = (unsigned short)__popc(mask);
    }
    __syncthreads();
    if (tid < 80) {
        int run = 0;
        for (int c = 0; c < 64; c++) {
            int v = chcnt[c * 80 + tid];
            chcnt[c * 80 + tid] = (unsigned short)run;
            run += v;
        }
        classcnt[tid] = run;
    }
    __syncthreads();
    if (tid == 0) {
        int off = 0;
        for (int cls = 0; cls < 80; cls++) { classoff[cls] = off; off += classcnt[cls]; }
    }
    __syncthreads();
    for (int c = wid; c < 64; c += 32) {
        int t = c * 32 + lane;
        unsigned L = labels[t];
        unsigned mask = __match_any_sync(0xffffffffu, L);
        if (L < 80) {
            int rank = __popc(mask & ((1u << lane) - 1u));
            clist[classoff[L] + chcnt[c * 80 + L] + rank] = (unsigned short)t;
        }
    }
    __syncthreads();

    // ---- B3: per-class greedy NMS (one warp per class) ----
    for (int cls = wid; cls < 80; cls += 32) {
        const unsigned short* list = clist + classoff[cls];
        int n = classcnt[cls];
        u64 kept = ~0ull;
        for (int i = 0; i < n; i++) {
            int il = i & 31, is = i >> 5;
            unsigned ki = __shfl_sync(0xffffffffu, (unsigned)((kept >> is) & 1ull), il);
            if (!ki) continue;
            int ti = list[i];
            float4 bi = boxes[ti];
            float ai = fmaxf(bi.z - bi.x, 0.f) * fmaxf(bi.w - bi.y, 0.f);
            for (int ss = is; ss * 32 + lane < n; ss++) {
                int e = ss * 32 + lane;
                if (e > i && ((kept >> ss) & 1ull)) {
                    float4 be = boxes[list[e]];
                    float ae = fmaxf(be.z - be.x, 0.f) * fmaxf(be.w - be.y, 0.f);
                    float lx = fmaxf(bi.x, be.x), ly = fmaxf(bi.y, be.y);
                    float rx = fminf(bi.z, be.z), ry = fminf(bi.w, be.w);
                    float iw = fmaxf(rx - lx, 0.f), ih = fmaxf(ry - ly, 0.f);
                    float inter = iw * ih;
                    float uni = ai + ae - inter;
                    if (inter / fmaxf(uni, 1e-9f) > NMS_T) kept &= ~(1ull << ss);
                }
            }
        }
        for (int ss = 0; ss * 32 + lane < n; ss++) {
            int e = ss * 32 + lane;
            keep[list[e]] = (unsigned char)((kept >> ss) & 1ull);
        }
    }
    __syncthreads();

    // ---- B4: final top-100 by (kept score, -t) and output ----
    for (int t = tid; t < KPRE; t += 1024) {
        float v = keep[t] ? scores[t] : -1.0f;
        unsigned u = __float_as_uint(v);
        u = (u & 0x80000000u) ? ~u : (u | 0x80000000u);
        keys[t] = ((u64)u << 32) | (u64)(0xFFFFFFFFu - (unsigned)t);
    }
    __syncthreads();
    for (int k2 = 2; k2 <= KPRE; k2 <<= 1) {
        for (int j = k2 >> 1; j; j >>= 1) {
            for (int i = tid; i < KPRE; i += 1024) {
                int ixj = i ^ j;
                if (ixj > i) {
                    u64 a = keys[i], c = keys[ixj];
                    bool up = ((i & k2) == 0);
                    if ((a < c) == up) { keys[i] = c; keys[ixj] = a; }
                }
            }
            __syncthreads();
        }
    }
    for (int t = tid; t < DET; t += 1024) {
        u64 key = keys[t];
        unsigned idx = 0xFFFFFFFFu - (unsigned)(key & 0xFFFFFFFFull);
        float sc = keep[idx] ? scores[idx] : -1.0f;
        float4 bx = boxes[idx];
        out[(b * DET + t) * 4 + 0] = bx.x;
        out[(b * DET + t) * 4 + 1] = bx.y;
        out[(b * DET + t) * 4 + 2] = bx.z;
        out[(b * DET + t) * 4 + 3] = bx.w;
        out[BI * DET * 4 + b * DET + t] = sc;
        out[BI * DET * 5 + b * DET + t] = (float)(labels[idx] + 1);
        out[BI * DET * 6 + b * DET + t] = (sc > 0.0f) ? 1.0f : 0.0f;
    }
}

// ---------------- launch ----------------
extern "C" void kernel_launch(void* const* d_in, const int* in_sizes, int n_in,
                              void* d_out, int out_size) {
    const float* logits = (const float*)d_in[0];
    const float* boxreg = (const float*)d_in[1];
    const float* props  = (const float*)d_in[2];
    float* out = (float*)d_out;

    cudaFuncSetAttribute(k_mega, cudaFuncAttributeMaxDynamicSharedMemorySize, 147456);

    k_reset<<<1, 32>>>();
    k_gen<<<(BI * PP * 32 + 255) / 256, 256>>>(logits, boxreg, props);
    k_mega<<<BI, 1024, 147456>>>(boxreg, props, out);
}

// round 4
// speedup vs baseline: 2.8189x; 1.2442x over previous
#include <cuda_runtime.h>
#include <math.h>

typedef unsigned long long u64;
typedef unsigned int u32;

#define BI 8
#define PP 2000
#define NC 81
#define CPP 80
#define CAP 16384
#define KPRE 2048
#define DET 100
#define NBIN 8192
#define BINSHIFT 50   // key>>50 == float bits [31:18]; sign==0 for scores>0
#define BCAP 8192
#define W_IMGF 1333.0f
#define H_IMGF 800.0f
#define SCORE_T 0.05f
#define NMS_T 0.5f
#define XFORM_CLIP 4.135166556742356f

// ---------------- device scratch (zero-initialized at load) ----------------
__device__ int g_cnt[BI];
__device__ u64 g_keys[BI][CAP];

// ---------------- helpers ----------------
__device__ __forceinline__ float4 decode_clip(float4 pr, float4 rel) {
    float w = pr.z - pr.x;
    float h = pr.w - pr.y;
    float cx = pr.x + 0.5f * w;
    float cy = pr.y + 0.5f * h;
    float dx = rel.x / 10.0f;
    float dy = rel.y / 10.0f;
    float dw = fminf(rel.z / 5.0f, XFORM_CLIP);
    float dh = fminf(rel.w / 5.0f, XFORM_CLIP);
    float pcx = dx * w + cx;
    float pcy = dy * h + cy;
    float pw = expf(dw) * w;
    float ph = expf(dh) * h;
    float x1 = fminf(fmaxf(pcx - 0.5f * pw, 0.0f), W_IMGF);
    float y1 = fminf(fmaxf(pcy - 0.5f * ph, 0.0f), H_IMGF);
    float x2 = fminf(fmaxf(pcx + 0.5f * pw, 0.0f), W_IMGF);
    float y2 = fminf(fmaxf(pcy + 0.5f * ph, 0.0f), H_IMGF);
    return make_float4(x1, y1, x2, y2);
}

__device__ __forceinline__ u64 sel_mm(u64 v, u64 o, bool takeMax) {
    return takeMax ? (v > o ? v : o) : (v < o ? v : o);
}

// ---------------- K1: softmax + candidate gen (warp-aggregated atomics) --
__global__ void k_gen(const float* __restrict__ logits,
                      const float* __restrict__ boxreg,
                      const float* __restrict__ props) {
    int gw = (blockIdx.x * blockDim.x + threadIdx.x) >> 5;
    int lane = threadIdx.x & 31;
    if (gw >= BI * PP) return;
    int b = gw / PP;
    int p = gw - b * PP;

    const float* lrow = logits + (long long)gw * NC;
    float l0 = lrow[lane];
    float l1 = lrow[lane + 32];
    float l2 = (lane + 64 < NC) ? lrow[lane + 64] : -1e30f;

    float m = fmaxf(l0, fmaxf(l1, l2));
    #pragma unroll
    for (int o = 16; o; o >>= 1) m = fmaxf(m, __shfl_xor_sync(0xffffffffu, m, o));
    float e0 = expf(l0 - m);
    float e1 = expf(l1 - m);
    float e2 = (lane + 64 < NC) ? expf(l2 - m) : 0.0f;
    float s = e0 + e1 + e2;
    #pragma unroll
    for (int o = 16; o; o >>= 1) s += __shfl_xor_sync(0xffffffffu, s, o);

    float4 pr = reinterpret_cast<const float4*>(props)[gw];

    bool ok[3];
    float sc[3];
    #pragma unroll
    for (int r = 0; r < 3; r++) {
        int ci = lane + r * 32;
        float e = (r == 0) ? e0 : ((r == 1) ? e1 : e2);
        ok[r] = false;
        sc[r] = 0.0f;
        if (ci >= 1 && ci < NC) {
            float score = e / s;
            if (score > SCORE_T) {
                float4 rel = reinterpret_cast<const float4*>(boxreg)[(long long)gw * NC + ci];
                float4 bx = decode_clip(pr, rel);
                if ((bx.z - bx.x) >= 0.01f && (bx.w - bx.y) >= 0.01f) {
                    ok[r] = true;
                    sc[r] = score;
                }
            }
        }
    }

    unsigned bal[3];
    bal[0] = __ballot_sync(0xffffffffu, ok[0]);
    bal[1] = __ballot_sync(0xffffffffu, ok[1]);
    bal[2] = __ballot_sync(0xffffffffu, ok[2]);
    int cnt0 = __popc(bal[0]);
    int cnt1 = __popc(bal[1]);
    int tot = cnt0 + cnt1 + __popc(bal[2]);
    int base = 0;
    if (lane == 0 && tot) base = atomicAdd(&g_cnt[b], tot);
    base = __shfl_sync(0xffffffffu, base, 0);

    unsigned below = (1u << lane) - 1u;
    #pragma unroll
    for (int r = 0; r < 3; r++) {
        if (ok[r]) {
            int off = __popc(bal[r] & below) + ((r > 0) ? cnt0 : 0) + ((r > 1) ? cnt1 : 0);
            int slot = base + off;
            if (slot < CAP) {
                unsigned idx = (unsigned)(p * CPP + (lane + r * 32 - 1));
                g_keys[b][slot] = ((u64)__float_as_uint(sc[r]) << 32) |
                                  (u64)(0xFFFFFFFFu - idx);
            }
        }
    }
}

// ---------------- K2: mega kernel ----------------
__global__ void __launch_bounds__(1024, 1)
k_mega(const float* __restrict__ boxreg,
       const float* __restrict__ props,
       float* __restrict__ out) {
    extern __shared__ char sm[];
    u64* keys = (u64*)sm;
    char* reg2 = sm + 16384;
    int* hist = (int*)reg2;
    u64* bound = (u64*)reg2;
    float4* boxes = (float4*)reg2;
    float* scores = (float*)(reg2 + 32768);
    unsigned char* labels = (unsigned char*)(reg2 + 40960);
    unsigned short* clist = (unsigned short*)(reg2 + 43008);
    unsigned short* chcnt = (unsigned short*)(reg2 + 47104);
    int* classoff = (int*)(reg2 + 57600);
    int* classcnt = classoff + 80;
    unsigned char* keep = (unsigned char*)(reg2 + 58368);

    __shared__ int s_t, s_A, s_R, aCtr, bCtr, wsum[32];

    const int tid = threadIdx.x;
    const int lane = tid & 31;
    const int wid = tid >> 5;
    const int b = blockIdx.x;
    const int cnt = min(g_cnt[b], CAP);
    const int K = min(cnt, KPRE);

    // ---- A1: histogram on float bits [30:18] ----
    for (int i = tid; i < NBIN; i += 1024) hist[i] = 0;
    if (tid == 0) { s_t = 0x7FFFFFFF; s_A = 0; s_R = 0; aCtr = 0; bCtr = 0; }
    __syncthreads();
    for (int i = tid; i < cnt; i += 1024) {
        int bin = (int)(g_keys[b][i] >> BINSHIFT);
        atomicAdd(&hist[bin], 1);
    }
    __syncthreads();

    // ---- A2: descending scan; find rank-K crossing bin ----
    {
        const int BPT = NBIN / 1024;
        int localsum = 0;
        int bhi = NBIN - 1 - BPT * tid;
        #pragma unroll
        for (int j = 0; j < BPT; j++) localsum += hist[bhi - j];
        int v = localsum;
        #pragma unroll
        for (int o = 1; o < 32; o <<= 1) {
            int n = __shfl_up_sync(0xffffffffu, v, o);
            if (lane >= o) v += n;
        }
        if (lane == 31) wsum[wid] = v;
        __syncthreads();
        if (wid == 0) {
            int w = wsum[lane];
            #pragma unroll
            for (int o = 1; o < 32; o <<= 1) {
                int n = __shfl_up_sync(0xffffffffu, w, o);
                if (lane >= o) w += n;
            }
            wsum[lane] = w;
        }
        __syncthreads();
        int incl = v + ((wid > 0) ? wsum[wid - 1] : 0);
        int excl = incl - localsum;
        if (K > 0 && excl < K && K <= incl) {
            int run = excl;
            for (int j = 0; j < BPT; j++) {
                int bin = bhi - j;
                int h = hist[bin];
                if (run < K && K <= run + h) { s_t = bin; s_A = run; s_R = K - run; }
                run += h;
            }
        }
    }
    __syncthreads();
    const int tbin = s_t, A = s_A, R = s_R;
    __syncthreads();  // hist dead; bound overlays it

    // ---- A3: compact above-threshold keys; gather boundary bin ----
    for (int i = tid; i < cnt; i += 1024) {
        u64 key = g_keys[b][i];
        int bin = (int)(key >> BINSHIFT);
        if (bin > tbin) {
            int pos = atomicAdd(&aCtr, 1);
            keys[pos] = key;
        } else if (bin == tbin) {
            int pos = atomicAdd(&bCtr, 1);
            if (pos < BCAP) bound[pos] = key;
        }
    }
    __syncthreads();

    // ---- A4: sort boundary bin desc, keep top R ----
    int m = min(bCtr, BCAP);
    if (m > 0) {
        int M = 1;
        while (M < m) M <<= 1;
        for (int i = m + tid; i < M; i += 1024) bound[i] = 0ull;
        __syncthreads();
        for (int k2 = 2; k2 <= M; k2 <<= 1) {
            for (int j = k2 >> 1; j; j >>= 1) {
                for (int i = tid; i < M; i += 1024) {
                    int ixj = i ^ j;
                    if (ixj > i) {
                        u64 a = bound[i], c = bound[ixj];
                        bool up = ((i & k2) == 0);
                        if ((a < c) == up) { bound[i] = c; bound[ixj] = a; }
                    }
                }
                __syncthreads();
            }
        }
        for (int i = tid; i < R; i += 1024) keys[A + i] = bound[i];
    }
    for (int i = K + tid; i < KPRE; i += 1024) keys[i] = 0ull;
    __syncthreads();

    // ---- A5: descending bitonic sort of 2048 keys (hierarchical) ----
    // Phase 1: each warp sorts its 64-element block in registers
    // (stages k=2..64, comparator identical to the smem version:
    //  element x takes max iff ((x&k)==0) == ((x&j)==0)).
    {
        int base = wid * 64;
        u64 r0 = keys[base + lane];
        u64 r1 = keys[base + lane + 32];
        #pragma unroll
        for (int k2 = 2; k2 <= 32; k2 <<= 1) {
            #pragma unroll
            for (int j = k2 >> 1; j; j >>= 1) {
                {
                    int x = lane;
                    u64 o = __shfl_xor_sync(0xffffffffu, r0, j);
                    r0 = sel_mm(r0, o, ((x & k2) == 0) == ((x & j) == 0));
                }
                {
                    int x = lane + 32;
                    u64 o = __shfl_xor_sync(0xffffffffu, r1, j);
                    r1 = sel_mm(r1, o, ((x & k2) == 0) == ((x & j) == 0));
                }
            }
        }
        {   // k = 64 : j=32 crosses r0/r1 within thread; direction from global bit6
            bool up = ((wid & 1) == 0);
            u64 lo = (r0 < r1) ? r0 : r1;
            u64 hi = (r0 < r1) ? r1 : r0;
            r0 = up ? hi : lo;
            r1 = up ? lo : hi;
            #pragma unroll
            for (int j = 16; j; j >>= 1) {
                bool tkm = up == ((lane & j) == 0);
                u64 o0 = __shfl_xor_sync(0xffffffffu, r0, j);
                u64 o1 = __shfl_xor_sync(0xffffffffu, r1, j);
                r0 = sel_mm(r0, o0, tkm);
                r1 = sel_mm(r1, o1, tkm);
            }
        }
        keys[base + lane] = r0;
        keys[base + lane + 32] = r1;
    }
    __syncthreads();
    // Phase 2: merge stages k=128..2048. j>=64 in smem (1 pair/thread),
    // j<=32 tail fused in registers per warp block.
    for (int k2 = 128; k2 <= KPRE; k2 <<= 1) {
        for (int j = k2 >> 1; j >= 64; j >>= 1) {
            int i = ((tid & ~(j - 1)) << 1) | (tid & (j - 1));
            u64 a = keys[i], c = keys[i + j];
            bool up = ((i & k2) == 0);
            if ((a < c) == up) { keys[i] = c; keys[i + j] = a; }
            __syncthreads();
        }
        {
            int base = wid * 64;
            bool up = ((base & k2) == 0);
            u64 r0 = keys[base + lane];
            u64 r1 = keys[base + lane + 32];
            u64 lo = (r0 < r1) ? r0 : r1;
            u64 hi = (r0 < r1) ? r1 : r0;
            r0 = up ? hi : lo;
            r1 = up ? lo : hi;
            #pragma unroll
            for (int j = 16; j; j >>= 1) {
                bool tkm = up == ((lane & j) == 0);
                u64 o0 = __shfl_xor_sync(0xffffffffu, r0, j);
                u64 o1 = __shfl_xor_sync(0xffffffffu, r1, j);
                r0 = sel_mm(r0, o0, tkm);
                r1 = sel_mm(r1, o1, tkm);
            }
            keys[base + lane] = r0;
            keys[base + lane + 32] = r1;
        }
        __syncthreads();
    }

    // ---- B1: decode boxes/scores/labels ----
    for (int t = tid; t < KPRE; t += 1024) {
        keep[t] = 0;
        if (t < K) {
            u64 key = keys[t];
            unsigned idx = 0xFFFFFFFFu - (unsigned)(key & 0xFFFFFFFFull);
            int p = idx / CPP;
            int cm1 = idx - p * CPP;
            int gw = b * PP + p;
            float4 pr = reinterpret_cast<const float4*>(props)[gw];
            float4 rel = reinterpret_cast<const float4*>(boxreg)[(long long)gw * NC + cm1 + 1];
            boxes[t] = decode_clip(pr, rel);
            scores[t] = __uint_as_float((unsigned)(key >> 32));
            labels[t] = (unsigned char)cm1;
        } else {
            boxes[t] = make_float4(0.f, 0.f, 0.f, 0.f);
            scores[t] = -1.0f;
            labels[t] = 0xFF;
        }
    }
    for (int i = tid; i < 64 * 80; i += 1024) chcnt[i] = 0;
    __syncthreads();

    // ---- B2: stable counting sort by class (match_any ranks) ----
    for (int c = wid; c < 64; c += 32) {
        int t = c * 32 + lane;
        unsigned L = labels[t];
        unsigned mask = __match_any_sync(0xffffffffu, L);
        int leader = __ffs(mask) - 1;
        if (L < 80 && lane == leader) chcnt[c * 80 + L] = (unsigned short)__popc(mask);
    }
    __syncthreads();
    if (tid < 80) {
        int run = 0;
        for (int c = 0; c < 64; c++) {
            int v = chcnt[c * 80 + tid];
            chcnt[c * 80 + tid] = (unsigned short)run;
            run += v;
        }
        classcnt[tid] = run;
    }
    __syncthreads();
    if (tid == 0) {
        int off = 0;
        for (int cls = 0; cls < 80; cls++) { classoff[cls] = off; off += classcnt[cls]; }
    }
    __syncthreads();
    for (int c = wid; c < 64; c += 32) {
        int t = c * 32 + lane;
        unsigned L = labels[t];
        unsigned mask = __match_any_sync(0xffffffffu, L);
        if (L < 80) {
            int rank = __popc(mask & ((1u << lane) - 1u));
            clist[classoff[L] + chcnt[c * 80 + L] + rank] = (unsigned short)t;
        }
    }
    __syncthreads();

    // ---- B3: per-class greedy NMS (one warp per class) ----
    for (int cls = wid; cls < 80; cls += 32) {
        const unsigned short* list = clist + classoff[cls];
        int n = classcnt[cls];
        u64 kept = ~0ull;
        for (int i = 0; i < n; i++) {
            int il = i & 31, is = i >> 5;
            unsigned ki = __shfl_sync(0xffffffffu, (unsigned)((kept >> is) & 1ull), il);
            if (!ki) continue;
            int ti = list[i];
            float4 bi = boxes[ti];
            float ai = fmaxf(bi.z - bi.x, 0.f) * fmaxf(bi.w - bi.y, 0.f);
            for (int ss = is; ss * 32 + lane < n; ss++) {
                int e = ss * 32 + lane;
                if (e > i && ((kept >> ss) & 1ull)) {
                    float4 be = boxes[list[e]];
                    float ae = fmaxf(be.z - be.x, 0.f) * fmaxf(be.w - be.y, 0.f);
                    float lx = fmaxf(bi.x, be.x), ly = fmaxf(bi.y, be.y);
                    float rx = fminf(bi.z, be.z), ry = fminf(bi.w, be.w);
                    float iw = fmaxf(rx - lx, 0.f), ih = fmaxf(ry - ly, 0.f);
                    float inter = iw * ih;
                    float uni = ai + ae - inter;
                    if (inter / fmaxf(uni, 1e-9f) > NMS_T) kept &= ~(1ull << ss);
                }
            }
        }
        for (int ss = 0; ss * 32 + lane < n; ss++) {
            int e = ss * 32 + lane;
            keep[list[e]] = (unsigned char)((kept >> ss) & 1ull);
        }
    }
    __syncthreads();

    // ---- B4: top-100 via stable compaction (NO sort needed) ----
    // Final comparator (kept?score:-1, -t) is exactly refined by t-order:
    // kept entries (t asc) then non-kept (t asc).
    {
        unsigned b0 = __ballot_sync(0xffffffffu, keep[wid * 64 + lane] != 0);
        unsigned b1 = __ballot_sync(0xffffffffu, keep[wid * 64 + 32 + lane] != 0);
        int wc = __popc(b0) + __popc(b1);
        if (lane == 0) wsum[wid] = wc;
        __syncthreads();
        if (wid == 0) {
            int w = wsum[lane];
            #pragma unroll
            for (int o = 1; o < 32; o <<= 1) {
                int n = __shfl_up_sync(0xffffffffu, w, o);
                if (lane >= o) w += n;
            }
            wsum[lane] = w;
        }
        __syncthreads();
        int warpbase = (wid > 0) ? wsum[wid - 1] : 0;
        int keptTotal = wsum[31];
        unsigned below = (1u << lane) - 1u;

        #pragma unroll
        for (int half = 0; half < 2; half++) {
            int t = wid * 64 + half * 32 + lane;
            int r = warpbase + ((half == 0)
                        ? __popc(b0 & below)
                        : (__popc(b0) + __popc(b1 & below)));
            bool kp = keep[t] != 0;
            int slot = kp ? r : (keptTotal + (t - r));
            if (slot < DET) {
                float sc = kp ? scores[t] : -1.0f;
                float4 bx = boxes[t];
                out[(b * DET + slot) * 4 + 0] = bx.x;
                out[(b * DET + slot) * 4 + 1] = bx.y;
                out[(b * DET + slot) * 4 + 2] = bx.z;
                out[(b * DET + slot) * 4 + 3] = bx.w;
                out[BI * DET * 4 + b * DET + slot] = sc;
                out[BI * DET * 5 + b * DET + slot] = (float)(labels[t] + 1);
                out[BI * DET * 6 + b * DET + slot] = kp ? 1.0f : 0.0f;
            }
        }
    }

    // ---- reset counter for next graph replay ----
    __syncthreads();
    if (tid == 0) g_cnt[b] = 0;
}

// ---------------- launch ----------------
extern "C" void kernel_launch(void* const* d_in, const int* in_sizes, int n_in,
                              void* d_out, int out_size) {
    const float* logits = (const float*)d_in[0];
    const float* boxreg = (const float*)d_in[1];
    const float* props  = (const float*)d_in[2];
    float* out = (float*)d_out;

    cudaFuncSetAttribute(k_mega, cudaFuncAttributeMaxDynamicSharedMemorySize, 147456);

    k_gen<<<(BI * PP * 32 + 255) / 256, 256>>>(logits, boxreg, props);
    k_mega<<<BI, 1024, 147456>>>(boxreg, props, out);
}

// round 5
// speedup vs baseline: 3.7940x; 1.3459x over previous
#include <cuda_runtime.h>
#include <math.h>

typedef unsigned long long u64;
typedef unsigned int u32;

#define BI 8
#define PP 2000
#define NC 81
#define CPP 80
#define CAP 16384
#define KPRE 2048
#define DET 100
#define NBIN 8192
#define BINSHIFT 50   // key>>50 == float bits [31:18]; sign==0 for scores>0
#define BCAP 8192
#define W_IMGF 1333.0f
#define H_IMGF 800.0f
#define SCORE_T 0.05f
#define NMS_T 0.5f
#define XFORM_CLIP 4.135166556742356f

// ---------------- device scratch (zero-initialized at load) ----------------
__device__ int g_cnt[BI];
__device__ u64 g_keys[BI][CAP];
__device__ float4 g_boxes[BI][KPRE];
__device__ float g_scores[BI][KPRE];
__device__ int g_labels[BI][KPRE];          // class-1, or 0xFF for padding
__device__ unsigned short g_clist[BI][KPRE];
__device__ int g_classoff[BI][CPP];
__device__ int g_classcnt[BI][CPP];
__device__ unsigned char g_keep[BI][KPRE];
__device__ int g_K[BI];

// ---------------- helpers ----------------
__device__ __forceinline__ float4 decode_clip(float4 pr, float4 rel) {
    float w = pr.z - pr.x;
    float h = pr.w - pr.y;
    float cx = pr.x + 0.5f * w;
    float cy = pr.y + 0.5f * h;
    float dx = rel.x / 10.0f;
    float dy = rel.y / 10.0f;
    float dw = fminf(rel.z / 5.0f, XFORM_CLIP);
    float dh = fminf(rel.w / 5.0f, XFORM_CLIP);
    float pcx = dx * w + cx;
    float pcy = dy * h + cy;
    float pw = expf(dw) * w;
    float ph = expf(dh) * h;
    float x1 = fminf(fmaxf(pcx - 0.5f * pw, 0.0f), W_IMGF);
    float y1 = fminf(fmaxf(pcy - 0.5f * ph, 0.0f), H_IMGF);
    float x2 = fminf(fmaxf(pcx + 0.5f * pw, 0.0f), W_IMGF);
    float y2 = fminf(fmaxf(pcy + 0.5f * ph, 0.0f), H_IMGF);
    return make_float4(x1, y1, x2, y2);
}

__device__ __forceinline__ u64 sel_mm(u64 v, u64 o, bool takeMax) {
    return takeMax ? (v > o ? v : o) : (v < o ? v : o);
}

// ---------------- K1: softmax + candidate gen ----------------
__global__ void k_gen(const float* __restrict__ logits,
                      const float* __restrict__ boxreg,
                      const float* __restrict__ props) {
    int gw = (blockIdx.x * blockDim.x + threadIdx.x) >> 5;
    int lane = threadIdx.x & 31;
    if (gw >= BI * PP) return;
    int b = gw / PP;
    int p = gw - b * PP;

    const float* lrow = logits + (long long)gw * NC;
    float l0 = lrow[lane];
    float l1 = lrow[lane + 32];
    float l2 = (lane + 64 < NC) ? lrow[lane + 64] : -1e30f;

    float m = fmaxf(l0, fmaxf(l1, l2));
    #pragma unroll
    for (int o = 16; o; o >>= 1) m = fmaxf(m, __shfl_xor_sync(0xffffffffu, m, o));
    float e0 = expf(l0 - m);
    float e1 = expf(l1 - m);
    float e2 = (lane + 64 < NC) ? expf(l2 - m) : 0.0f;
    float s = e0 + e1 + e2;
    #pragma unroll
    for (int o = 16; o; o >>= 1) s += __shfl_xor_sync(0xffffffffu, s, o);

    float4 pr = reinterpret_cast<const float4*>(props)[gw];

    bool ok[3];
    float sc[3];
    #pragma unroll
    for (int r = 0; r < 3; r++) {
        int ci = lane + r * 32;
        float e = (r == 0) ? e0 : ((r == 1) ? e1 : e2);
        ok[r] = false;
        sc[r] = 0.0f;
        if (ci >= 1 && ci < NC) {
            float score = e / s;
            if (score > SCORE_T) {
                float4 rel = reinterpret_cast<const float4*>(boxreg)[(long long)gw * NC + ci];
                float4 bx = decode_clip(pr, rel);
                if ((bx.z - bx.x) >= 0.01f && (bx.w - bx.y) >= 0.01f) {
                    ok[r] = true;
                    sc[r] = score;
                }
            }
        }
    }

    unsigned bal[3];
    bal[0] = __ballot_sync(0xffffffffu, ok[0]);
    bal[1] = __ballot_sync(0xffffffffu, ok[1]);
    bal[2] = __ballot_sync(0xffffffffu, ok[2]);
    int cnt0 = __popc(bal[0]);
    int cnt1 = __popc(bal[1]);
    int tot = cnt0 + cnt1 + __popc(bal[2]);
    int base = 0;
    if (lane == 0 && tot) base = atomicAdd(&g_cnt[b], tot);
    base = __shfl_sync(0xffffffffu, base, 0);

    unsigned below = (1u << lane) - 1u;
    #pragma unroll
    for (int r = 0; r < 3; r++) {
        if (ok[r]) {
            int off = __popc(bal[r] & below) + ((r > 0) ? cnt0 : 0) + ((r > 1) ? cnt1 : 0);
            int slot = base + off;
            if (slot < CAP) {
                unsigned idx = (unsigned)(p * CPP + (lane + r * 32 - 1));
                g_keys[b][slot] = ((u64)__float_as_uint(sc[r]) << 32) |
                                  (u64)(0xFFFFFFFFu - idx);
            }
        }
    }
}

// ---------------- K2: select top-2048, sort, decode, class lists ----------
__global__ void __launch_bounds__(1024, 1)
k_select(const float* __restrict__ boxreg,
         const float* __restrict__ props) {
    extern __shared__ char sm[];
    u64* keys = (u64*)sm;
    char* reg2 = sm + 16384;
    int* hist = (int*)reg2;
    u64* bound = (u64*)reg2;
    unsigned short* chcnt = (unsigned short*)reg2;               // 64*80 u16
    int* classoff = (int*)(reg2 + 10240);
    int* classcnt = classoff + CPP;
    unsigned char* slab = (unsigned char*)(reg2 + 11008);        // labels[2048]

    __shared__ int s_t, s_A, s_R, aCtr, bCtr, wsum[32];

    const int tid = threadIdx.x;
    const int lane = tid & 31;
    const int wid = tid >> 5;
    const int b = blockIdx.x;
    const int cnt = min(g_cnt[b], CAP);
    const int K = min(cnt, KPRE);

    // ---- A1: histogram (match_any aggregated) ----
    for (int i = tid; i < NBIN; i += 1024) hist[i] = 0;
    if (tid == 0) { s_t = 0x7FFFFFFF; s_A = 0; s_R = 0; aCtr = 0; bCtr = 0; }
    __syncthreads();
    for (int base = 0; base < cnt; base += 1024) {
        int i = base + tid;
        int bin = (i < cnt) ? (int)(g_keys[b][i] >> BINSHIFT) : -1;
        unsigned mask = __match_any_sync(0xffffffffu, bin);
        if (bin >= 0 && lane == (__ffs(mask) - 1))
            atomicAdd(&hist[bin], __popc(mask));
    }
    __syncthreads();

    // ---- A2: descending scan; find rank-K crossing bin ----
    {
        const int BPT = NBIN / 1024;
        int localsum = 0;
        int bhi = NBIN - 1 - BPT * tid;
        #pragma unroll
        for (int j = 0; j < BPT; j++) localsum += hist[bhi - j];
        int v = localsum;
        #pragma unroll
        for (int o = 1; o < 32; o <<= 1) {
            int n = __shfl_up_sync(0xffffffffu, v, o);
            if (lane >= o) v += n;
        }
        if (lane == 31) wsum[wid] = v;
        __syncthreads();
        if (wid == 0) {
            int w = wsum[lane];
            #pragma unroll
            for (int o = 1; o < 32; o <<= 1) {
                int n = __shfl_up_sync(0xffffffffu, w, o);
                if (lane >= o) w += n;
            }
            wsum[lane] = w;
        }
        __syncthreads();
        int incl = v + ((wid > 0) ? wsum[wid - 1] : 0);
        int excl = incl - localsum;
        if (K > 0 && excl < K && K <= incl) {
            int run = excl;
            for (int j = 0; j < BPT; j++) {
                int bin = bhi - j;
                int h = hist[bin];
                if (run < K && K <= run + h) { s_t = bin; s_A = run; s_R = K - run; }
                run += h;
            }
        }
    }
    __syncthreads();
    const int tbin = s_t, A = s_A, R = s_R;
    __syncthreads();  // hist dead; bound overlays it

    // ---- A3: compact (warp-aggregated; order irrelevant, sorted later) ----
    for (int base = 0; base < cnt; base += 1024) {
        int i = base + tid;
        u64 key = (i < cnt) ? g_keys[b][i] : 0ull;
        int bin = (i < cnt) ? (int)(key >> BINSHIFT) : -1;
        bool above = bin > tbin;
        bool atb = bin == tbin;
        unsigned balA = __ballot_sync(0xffffffffu, above);
        unsigned balB = __ballot_sync(0xffffffffu, atb);
        int bA = 0, bB = 0;
        if (lane == 0) {
            if (balA) bA = atomicAdd(&aCtr, __popc(balA));
            if (balB) bB = atomicAdd(&bCtr, __popc(balB));
        }
        bA = __shfl_sync(0xffffffffu, bA, 0);
        bB = __shfl_sync(0xffffffffu, bB, 0);
        unsigned below = (1u << lane) - 1u;
        if (above) keys[bA + __popc(balA & below)] = key;
        else if (atb) {
            int pos = bB + __popc(balB & below);
            if (pos < BCAP) bound[pos] = key;
        }
    }
    __syncthreads();

    // ---- A4: sort boundary bin desc, keep top R ----
    int m = min(bCtr, BCAP);
    if (m > 0) {
        int M = 1;
        while (M < m) M <<= 1;
        for (int i = m + tid; i < M; i += 1024) bound[i] = 0ull;
        __syncthreads();
        for (int k2 = 2; k2 <= M; k2 <<= 1) {
            for (int j = k2 >> 1; j; j >>= 1) {
                for (int i = tid; i < M; i += 1024) {
                    int ixj = i ^ j;
                    if (ixj > i) {
                        u64 a = bound[i], c = bound[ixj];
                        bool up = ((i & k2) == 0);
                        if ((a < c) == up) { bound[i] = c; bound[ixj] = a; }
                    }
                }
                __syncthreads();
            }
        }
        for (int i = tid; i < R; i += 1024) keys[A + i] = bound[i];
    }
    for (int i = K + tid; i < KPRE; i += 1024) keys[i] = 0ull;
    __syncthreads();

    // ---- A5: descending bitonic sort of 2048 keys (hierarchical) ----
    {
        int base = wid * 64;
        u64 r0 = keys[base + lane];
        u64 r1 = keys[base + lane + 32];
        #pragma unroll
        for (int k2 = 2; k2 <= 32; k2 <<= 1) {
            #pragma unroll
            for (int j = k2 >> 1; j; j >>= 1) {
                {
                    int x = lane;
                    u64 o = __shfl_xor_sync(0xffffffffu, r0, j);
                    r0 = sel_mm(r0, o, ((x & k2) == 0) == ((x & j) == 0));
                }
                {
                    int x = lane + 32;
                    u64 o = __shfl_xor_sync(0xffffffffu, r1, j);
                    r1 = sel_mm(r1, o, ((x & k2) == 0) == ((x & j) == 0));
                }
            }
        }
        {
            bool up = ((wid & 1) == 0);
            u64 lo = (r0 < r1) ? r0 : r1;
            u64 hi = (r0 < r1) ? r1 : r0;
            r0 = up ? hi : lo;
            r1 = up ? lo : hi;
            #pragma unroll
            for (int j = 16; j; j >>= 1) {
                bool tkm = up == ((lane & j) == 0);
                u64 o0 = __shfl_xor_sync(0xffffffffu, r0, j);
                u64 o1 = __shfl_xor_sync(0xffffffffu, r1, j);
                r0 = sel_mm(r0, o0, tkm);
                r1 = sel_mm(r1, o1, tkm);
            }
        }
        keys[base + lane] = r0;
        keys[base + lane + 32] = r1;
    }
    __syncthreads();
    for (int k2 = 128; k2 <= KPRE; k2 <<= 1) {
        for (int j = k2 >> 1; j >= 64; j >>= 1) {
            int i = ((tid & ~(j - 1)) << 1) | (tid & (j - 1));
            u64 a = keys[i], c = keys[i + j];
            bool up = ((i & k2) == 0);
            if ((a < c) == up) { keys[i] = c; keys[i + j] = a; }
            __syncthreads();
        }
        {
            int base = wid * 64;
            bool up = ((base & k2) == 0);
            u64 r0 = keys[base + lane];
            u64 r1 = keys[base + lane + 32];
            u64 lo = (r0 < r1) ? r0 : r1;
            u64 hi = (r0 < r1) ? r1 : r0;
            r0 = up ? hi : lo;
            r1 = up ? lo : hi;
            #pragma unroll
            for (int j = 16; j; j >>= 1) {
                bool tkm = up == ((lane & j) == 0);
                u64 o0 = __shfl_xor_sync(0xffffffffu, r0, j);
                u64 o1 = __shfl_xor_sync(0xffffffffu, r1, j);
                r0 = sel_mm(r0, o0, tkm);
                r1 = sel_mm(r1, o1, tkm);
            }
            keys[base + lane] = r0;
            keys[base + lane + 32] = r1;
        }
        __syncthreads();
    }

    // ---- B1: decode + write boxes/scores/labels to gmem ----
    for (int t = tid; t < KPRE; t += 1024) {
        if (t < K) {
            u64 key = keys[t];
            unsigned idx = 0xFFFFFFFFu - (unsigned)(key & 0xFFFFFFFFull);
            int p = idx / CPP;
            int cm1 = idx - p * CPP;
            int gw = b * PP + p;
            float4 pr = reinterpret_cast<const float4*>(props)[gw];
            float4 rel = reinterpret_cast<const float4*>(boxreg)[(long long)gw * NC + cm1 + 1];
            g_boxes[b][t] = decode_clip(pr, rel);
            g_scores[b][t] = __uint_as_float((unsigned)(key >> 32));
            g_labels[b][t] = cm1;
            slab[t] = (unsigned char)cm1;
        } else {
            g_boxes[b][t] = make_float4(0.f, 0.f, 0.f, 0.f);
            g_scores[b][t] = -1.0f;
            g_labels[b][t] = 0xFF;
            slab[t] = 0xFF;
        }
    }
    for (int i = tid; i < 64 * CPP; i += 1024) chcnt[i] = 0;
    __syncthreads();

    // ---- B2: stable counting sort by class -> g_clist ----
    for (int c = wid; c < 64; c += 32) {
        int t = c * 32 + lane;
        unsigned L = slab[t];
        unsigned mask = __match_any_sync(0xffffffffu, L);
        if (L < CPP && lane == (__ffs(mask) - 1))
            chcnt[c * CPP + L] = (unsigned short)__popc(mask);
    }
    __syncthreads();
    if (tid < CPP) {
        int run = 0;
        for (int c = 0; c < 64; c++) {
            int v = chcnt[c * CPP + tid];
            chcnt[c * CPP + tid] = (unsigned short)run;
            run += v;
        }
        classcnt[tid] = run;
        g_classcnt[b][tid] = run;
    }
    __syncthreads();
    if (tid == 0) {
        int off = 0;
        for (int cls = 0; cls < CPP; cls++) { classoff[cls] = off; off += classcnt[cls]; }
    }
    __syncthreads();
    if (tid < CPP) g_classoff[b][tid] = classoff[tid];
    for (int c = wid; c < 64; c += 32) {
        int t = c * 32 + lane;
        unsigned L = slab[t];
        unsigned mask = __match_any_sync(0xffffffffu, L);
        if (L < CPP) {
            int rank = __popc(mask & ((1u << lane) - 1u));
            g_clist[b][classoff[L] + chcnt[c * CPP + L] + rank] = (unsigned short)t;
        }
    }

    if (tid == 0) { g_K[b] = K; g_cnt[b] = 0; }
}

// ---------------- K3: per-class greedy NMS (one 32-thread block each) ----
__global__ void __launch_bounds__(32)
k_nms() {
    __shared__ float4 sbox[KPRE];
    __shared__ float sarea[KPRE];
    const int cls = blockIdx.x;
    const int b = blockIdx.y;
    const int lane = threadIdx.x;
    const int n = g_classcnt[b][cls];
    if (n == 0) return;
    const int off = g_classoff[b][cls];
    const unsigned short* list = &g_clist[b][off];

    for (int e = lane; e < n; e += 32) {
        float4 bx = g_boxes[b][list[e]];
        sbox[e] = bx;
        sarea[e] = fmaxf(bx.z - bx.x, 0.f) * fmaxf(bx.w - bx.y, 0.f);
    }
    __syncwarp();

    u64 kept = ~0ull;
    for (int i = 0; i < n; i++) {
        int il = i & 31, is = i >> 5;
        unsigned ki = __shfl_sync(0xffffffffu, (unsigned)((kept >> is) & 1ull), il);
        if (!ki) continue;
        float4 bi = sbox[i];
        float ai = sarea[i];
        for (int ss = is; ss * 32 + lane < n; ss++) {
            int e = ss * 32 + lane;
            if (e > i && ((kept >> ss) & 1ull)) {
                float4 be = sbox[e];
                float lx = fmaxf(bi.x, be.x), ly = fmaxf(bi.y, be.y);
                float rx = fminf(bi.z, be.z), ry = fminf(bi.w, be.w);
                float iw = fmaxf(rx - lx, 0.f), ih = fmaxf(ry - ly, 0.f);
                float inter = iw * ih;
                float uni = ai + sarea[e] - inter;
                if (inter / fmaxf(uni, 1e-9f) > NMS_T) kept &= ~(1ull << ss);
            }
        }
    }
    for (int ss = 0; ss * 32 + lane < n; ss++) {
        int e = ss * 32 + lane;
        g_keep[b][list[e]] = (unsigned char)((kept >> ss) & 1ull);
    }
}

// ---------------- K4: stable compaction + output ----------------
// Final comparator (kept?score:-1, -t) is exactly refined by t-order:
// kept entries (t asc) then non-kept (t asc).
__global__ void __launch_bounds__(1024)
k_out(float* __restrict__ out) {
    __shared__ int wsum[32];
    const int tid = threadIdx.x;
    const int lane = tid & 31;
    const int wid = tid >> 5;
    const int b = blockIdx.x;
    const int K = g_K[b];

    bool kp0 = (wid * 64 + lane) < K && g_keep[b][wid * 64 + lane];
    bool kp1 = (wid * 64 + 32 + lane) < K && g_keep[b][wid * 64 + 32 + lane];
    unsigned b0 = __ballot_sync(0xffffffffu, kp0);
    unsigned b1 = __ballot_sync(0xffffffffu, kp1);
    if (lane == 0) wsum[wid] = __popc(b0) + __popc(b1);
    __syncthreads();
    if (wid == 0) {
        int w = wsum[lane];
        #pragma unroll
        for (int o = 1; o < 32; o <<= 1) {
            int n = __shfl_up_sync(0xffffffffu, w, o);
            if (lane >= o) w += n;
        }
        wsum[lane] = w;
    }
    __syncthreads();
    int warpbase = (wid > 0) ? wsum[wid - 1] : 0;
    int keptTotal = wsum[31];
    unsigned below = (1u << lane) - 1u;

    #pragma unroll
    for (int half = 0; half < 2; half++) {
        int t = wid * 64 + half * 32 + lane;
        bool kp = (half == 0) ? kp0 : kp1;
        int r = warpbase + ((half == 0)
                    ? __popc(b0 & below)
                    : (__popc(b0) + __popc(b1 & below)));
        int slot = kp ? r : (keptTotal + (t - r));
        if (slot < DET) {
            float sc = kp ? g_scores[b][t] : -1.0f;
            float4 bx = g_boxes[b][t];
            out[(b * DET + slot) * 4 + 0] = bx.x;
            out[(b * DET + slot) * 4 + 1] = bx.y;
            out[(b * DET + slot) * 4 + 2] = bx.z;
            out[(b * DET + slot) * 4 + 3] = bx.w;
            out[BI * DET * 4 + b * DET + slot] = sc;
            out[BI * DET * 5 + b * DET + slot] = (float)(g_labels[b][t] + 1);
            out[BI * DET * 6 + b * DET + slot] = kp ? 1.0f : 0.0f;
        }
    }
}

// ---------------- launch ----------------
extern "C" void kernel_launch(void* const* d_in, const int* in_sizes, int n_in,
                              void* d_out, int out_size) {
    const float* logits = (const float*)d_in[0];
    const float* boxreg = (const float*)d_in[1];
    const float* props  = (const float*)d_in[2];
    float* out = (float*)d_out;

    cudaFuncSetAttribute(k_select, cudaFuncAttributeMaxDynamicSharedMemorySize, 147456);

    k_gen<<<(BI * PP * 32 + 255) / 256, 256>>>(logits, boxreg, props);
    k_select<<<BI, 1024, 147456>>>(boxreg, props);
    k_nms<<<dim3(CPP, BI), 32>>>();
    k_out<<<BI, 1024>>>(out);
}